// round 15
// baseline (speedup 1.0000x reference)
#include <cuda_runtime.h>
#include <cuda_fp16.h>

#define N_TOKS 32768
#define EMBED  512
#define NCLS   16
#define NBATCH 8
#define NHEAD  8
#define DHEAD  64
#define RDIM   128
#define SCALE  0.125f
#define TM     128

typedef unsigned int u32;

// fp16 tables (error sources: S/T/Q/P quantization ~2^-11 each)
__device__ __half g_Sh[NBATCH*RDIM*EMBED];   // [b][r][k]
__device__ __half g_Th[NBATCH*EMBED*RDIM];   // [b][e][r]
__device__ float g_C[NBATCH*RDIM];

// ---------------- PTX helpers (family-portable) ----------------
__device__ __forceinline__ u32 smem_u32(const void* p) {
    u32 a;
    asm("{ .reg .u64 t; cvta.to.shared.u64 t, %1; cvt.u32.u64 %0, t; }" : "=r"(a) : "l"(p));
    return a;
}
__device__ __forceinline__ void ldsm_x4(u32* r, u32 addr) {
    asm volatile("ldmatrix.sync.aligned.m8n8.x4.shared.b16 {%0,%1,%2,%3}, [%4];"
                 : "=r"(r[0]), "=r"(r[1]), "=r"(r[2]), "=r"(r[3]) : "r"(addr));
}
__device__ __forceinline__ void mma_f16(float* c, const u32* a, u32 b0, u32 b1) {
    asm volatile("mma.sync.aligned.m16n8k16.row.col.f32.f16.f16.f32 "
                 "{%0,%1,%2,%3}, {%4,%5,%6,%7}, {%8,%9}, {%0,%1,%2,%3};"
                 : "+f"(c[0]), "+f"(c[1]), "+f"(c[2]), "+f"(c[3])
                 : "r"(a[0]), "r"(a[1]), "r"(a[2]), "r"(a[3]), "r"(b0), "r"(b1));
}
__device__ __forceinline__ void cp16(u32 dst, const void* src) {
    asm volatile("cp.async.cg.shared.global [%0], [%1], 16;" :: "r"(dst), "l"(src));
}
__device__ __forceinline__ void cp_commit() {
    asm volatile("cp.async.commit_group;" ::: "memory");
}
__device__ __forceinline__ void cp_wait0() {
    asm volatile("cp.async.wait_group 0;" ::: "memory");
}
__device__ __forceinline__ u32 pack2h(float x, float y) {
    __half hx = __float2half_rn(x), hy = __float2half_rn(y);
    return (u32)__half_as_ushort(hx) | ((u32)__half_as_ushort(hy) << 16);
}

// ---------------------------------------------------------------------------
// Fused prep: per (mat,h,b): phase1 KP/VP slice in smem (e-chunks of 128,
// register double-buffered), then fold Wq->S(+C) or Wo->T with W prefetch.
// grid=128: mat=x&1, h=(x>>1)&7, b=(x>>4)&7
// ---------------------------------------------------------------------------
__global__ __launch_bounds__(256)
void prep_kernel(const float* __restrict__ key, const float* __restrict__ value,
                 const float* __restrict__ Wk, const float* __restrict__ bk,
                 const float* __restrict__ Wv, const float* __restrict__ bv,
                 const float* __restrict__ Wq, const float* __restrict__ bq,
                 const float* __restrict__ Wo) {
    __shared__ float Ks[16][129];
    __shared__ float KPs[16][65];
    __shared__ float Ws[64][129];

    const int x = blockIdx.x;
    const int mat = x & 1;
    const int h   = (x >> 1) & 7;
    const int b   = (x >> 4) & 7;
    const int tid = threadIdx.x;

    const float* src = mat ? value : key;
    const float* W1  = mat ? Wv : Wk;
    const float* b1  = mat ? bv : bk;

    // ---- phase 1: KP[l][d] = sum_e src[l,b,e]*W1[h*64+d,e] + b1 (in smem) ----
    const int d   = tid & 63;
    const int lg4 = tid >> 6;
    {
        float acc[4] = {0.f, 0.f, 0.f, 0.f};
        float4 kbuf[2], wbuf[8];
        #pragma unroll
        for (int i = 0; i < 2; i++) {          // 16 rows x 32 c4
            int id = tid + i*256; int row = id >> 5, c4 = id & 31;
            kbuf[i] = *(const float4*)(src + (row*NBATCH + b)*EMBED + c4*4);
        }
        #pragma unroll
        for (int i = 0; i < 8; i++) {          // 64 d x 32 c4
            int id = tid + i*256; int dd = id >> 5, c4 = id & 31;
            wbuf[i] = *(const float4*)(W1 + (h*DHEAD + dd)*EMBED + c4*4);
        }
        for (int e0 = 0; e0 < EMBED; e0 += 128) {
            #pragma unroll
            for (int i = 0; i < 2; i++) {
                int id = tid + i*256; int row = id >> 5, c4 = id & 31;
                Ks[row][c4*4+0] = kbuf[i].x; Ks[row][c4*4+1] = kbuf[i].y;
                Ks[row][c4*4+2] = kbuf[i].z; Ks[row][c4*4+3] = kbuf[i].w;
            }
            #pragma unroll
            for (int i = 0; i < 8; i++) {
                int id = tid + i*256; int dd = id >> 5, c4 = id & 31;
                Ws[dd][c4*4+0] = wbuf[i].x; Ws[dd][c4*4+1] = wbuf[i].y;
                Ws[dd][c4*4+2] = wbuf[i].z; Ws[dd][c4*4+3] = wbuf[i].w;
            }
            __syncthreads();
            if (e0 + 128 < EMBED) {
                #pragma unroll
                for (int i = 0; i < 2; i++) {
                    int id = tid + i*256; int row = id >> 5, c4 = id & 31;
                    kbuf[i] = *(const float4*)(src + (row*NBATCH + b)*EMBED + e0 + 128 + c4*4);
                }
                #pragma unroll
                for (int i = 0; i < 8; i++) {
                    int id = tid + i*256; int dd = id >> 5, c4 = id & 31;
                    wbuf[i] = *(const float4*)(W1 + (h*DHEAD + dd)*EMBED + e0 + 128 + c4*4);
                }
            }
            #pragma unroll 8
            for (int e = 0; e < 128; e++) {
                float wv = Ws[d][e];
                #pragma unroll
                for (int i = 0; i < 4; i++) acc[i] += Ks[lg4*4 + i][e] * wv;
            }
            __syncthreads();
        }
        float bias = b1[h*DHEAD + d];
        #pragma unroll
        for (int i = 0; i < 4; i++) KPs[lg4*4 + i][d] = acc[i] + bias;
    }
    __syncthreads();

    // ---- fold: 4 f-chunks of 128, W prefetched in registers ----
    const int fcc = tid & 127, lg = tid >> 7;
    if (mat == 0 && tid < 16) {
        float c = 0.f;
        #pragma unroll 8
        for (int dd = 0; dd < DHEAD; dd++) c += KPs[tid][dd] * bq[h*DHEAD + dd];
        g_C[b*RDIM + h*NCLS + tid] = c * SCALE;
    }

    float4 fw[8];
    // prefetch fc=0
    if (mat == 0) {
        #pragma unroll
        for (int i = 0; i < 8; i++) {
            int idx = tid + i*256; int dd = idx >> 5, f4 = idx & 31;
            fw[i] = *(const float4*)(Wq + (h*DHEAD + dd)*EMBED + f4*4);
        }
    } else {
        #pragma unroll
        for (int i = 0; i < 8; i++) {
            int idx = tid + i*256; int e = idx >> 4, d4 = idx & 15;
            fw[i] = *(const float4*)(Wo + e*EMBED + h*DHEAD + d4*4);
        }
    }

    for (int fc = 0; fc < 4; fc++) {
        const int f0 = fc * 128;
        if (mat == 0) {
            #pragma unroll
            for (int i = 0; i < 8; i++) {      // Wq slice 64d x 128f
                int idx = tid + i*256; int dd = idx >> 5, f4 = idx & 31;
                Ws[dd][f4*4+0] = fw[i].x; Ws[dd][f4*4+1] = fw[i].y;
                Ws[dd][f4*4+2] = fw[i].z; Ws[dd][f4*4+3] = fw[i].w;
            }
        } else {
            #pragma unroll
            for (int i = 0; i < 8; i++) {      // Wo slice: 128e rows x 64d
                int idx = tid + i*256; int e = idx >> 4, d4 = idx & 15;
                Ws[d4*4+0][e] = fw[i].x; Ws[d4*4+1][e] = fw[i].y;
                Ws[d4*4+2][e] = fw[i].z; Ws[d4*4+3][e] = fw[i].w;
            }
        }
        __syncthreads();
        if (fc < 3) {
            const int f1 = f0 + 128;
            if (mat == 0) {
                #pragma unroll
                for (int i = 0; i < 8; i++) {
                    int idx = tid + i*256; int dd = idx >> 5, f4 = idx & 31;
                    fw[i] = *(const float4*)(Wq + (h*DHEAD + dd)*EMBED + f1 + f4*4);
                }
            } else {
                #pragma unroll
                for (int i = 0; i < 8; i++) {
                    int idx = tid + i*256; int e = idx >> 4, d4 = idx & 15;
                    fw[i] = *(const float4*)(Wo + (f1 + e)*EMBED + h*DHEAD + d4*4);
                }
            }
        }

        float a2[8] = {0,0,0,0,0,0,0,0};
        #pragma unroll 8
        for (int dd = 0; dd < DHEAD; dd++) {
            float wv = Ws[dd][fcc];
            #pragma unroll
            for (int i = 0; i < 8; i++) a2[i] += KPs[lg*8 + i][dd] * wv;
        }

        if (mat == 0) {
            #pragma unroll
            for (int i = 0; i < 8; i++) {
                int r = h*NCLS + lg*8 + i;
                g_Sh[(b*RDIM + r)*EMBED + f0 + fcc] = __float2half_rn(a2[i] * SCALE);
            }
        } else {
            u32 hw[4];
            #pragma unroll
            for (int i = 0; i < 4; i++)
                hw[i] = pack2h(a2[2*i], a2[2*i+1]);
            long long ofs = ((long long)(b*EMBED + f0 + fcc))*RDIM + h*NCLS + lg*8;
            *(uint4*)&g_Th[ofs] = make_uint4(hw[0], hw[1], hw[2], hw[3]);
        }
        __syncthreads();
    }
}

// ---------------------------------------------------------------------------
// Main attention kernel: 128 tokens/block, 8 warps, double-buffered cp.async.
// Single fp16 pass. Phase A k-chunk 64 (8 iters); Phase C e-chunk 128 (4 iters).
// ---------------------------------------------------------------------------
#define STG_SZ  36864
#define QH_O    0        // 128 rows x 144B (128B data + 16 pad)
#define SH_O    18432    // 128 rows x 144B
#define TH_O    0        // Phase C alias: 128 rows x 272B (256B + 16 pad)
#define SM_BOS  73728
#define SM_CS   75776
#define SM_BT   76288
#define SMEM_ATTN 76800
#define NC_A 8
#define NC_C 4

__device__ __forceinline__ void stage_S(u32 sb, u32 stg, int b, int k0, int tid) {
    #pragma unroll
    for (int i = 0; i < 4; i++) {             // 128 rows x 8 parts of 16B
        int o = tid + i*256;
        int rr = o >> 3, part = o & 7;
        const __half* src = g_Sh + (long long)(b*RDIM + rr)*EMBED + k0 + part*8;
        cp16(sb + stg + SH_O + rr*144 + part*16, src);
    }
}
__device__ __forceinline__ void stage_T(u32 sb, u32 stg, int b, int e0, int tid) {
    #pragma unroll
    for (int i = 0; i < 8; i++) {             // 128 rows x 16 parts of 16B
        int o = tid + i*256;
        int rr = o >> 4, part = o & 15;
        const __half* src = g_Th + (long long)(b*EMBED + e0 + rr)*RDIM + part*8;
        cp16(sb + stg + TH_O + rr*272 + part*16, src);
    }
}
// load 64-k Q chunk (f32) and convert to fp16 tile (two half-passes, low liveness)
__device__ __forceinline__ void ldg_cvt_Q(const float* __restrict__ query,
                                          char* sm, u32 stg, int n0, int k0, int tid) {
    #pragma unroll
    for (int half = 0; half < 2; half++) {
        float4 qv[4];
        #pragma unroll
        for (int i = 0; i < 4; i++) {
            int id = tid + (half*4 + i)*256;   // 2048 float4 = 128 rows x 16 c4
            int row = id >> 4, c4 = id & 15;
            qv[i] = *(const float4*)(query + (long long)(n0 + row)*EMBED + k0 + c4*4);
        }
        #pragma unroll
        for (int i = 0; i < 4; i++) {
            int id = tid + (half*4 + i)*256;
            int row = id >> 4, c4 = id & 15;
            uint2 hv;
            hv.x = pack2h(qv[i].x, qv[i].y);
            hv.y = pack2h(qv[i].z, qv[i].w);
            *(uint2*)(sm + stg + QH_O + row*144 + c4*8) = hv;
        }
    }
}

__global__ __launch_bounds__(256, 2)
void attn_mma_kernel(const float* __restrict__ query,
                     const int*   __restrict__ bidx,
                     const float* __restrict__ bo,
                     float*       __restrict__ out) {
    extern __shared__ char sm[];
    const u32 sb = smem_u32(sm);

    const int tid  = threadIdx.x;
    const int lane = tid & 31, wid = tid >> 5;
    const int n0   = blockIdx.x * TM;
    const int m0   = wid * 16;
    const int qr   = lane >> 2;
    const int qc   = lane & 3;

    float* bos = (float*)(sm + SM_BOS);
    float* Cs  = (float*)(sm + SM_CS);
    int*   bt  = (int*)(sm + SM_BT);
    bos[tid]       = bo[tid];
    bos[tid + 256] = bo[tid + 256];
    if (tid < TM) bt[tid] = bidx[n0 + tid];
    __syncthreads();
    const int b_lo = bt[0], b_hi = bt[TM - 1];

    const u32 arow    = m0 + (lane & 15);
    const u32 aoff    = (u32)(lane >> 4) << 4;          // 0/16B: k+0 / k+8
    const u32 browoff = ((lane >> 4) << 3) + (lane & 7);
    const u32 boff    = (u32)((lane >> 3) & 1) << 4;    // 0/16B

    for (int b = b_lo; b <= b_hi; b++) {
        if (tid < 128) Cs[tid] = g_C[b*RDIM + tid];

        // ================= Phase A: scores = Q @ S_b^T (pipelined) ==========
        float acc[16][4];
        #pragma unroll
        for (int i = 0; i < 16; i++)
            #pragma unroll
            for (int j = 0; j < 4; j++) acc[i][j] = 0.f;

        stage_S(sb, 0, b, 0, tid); cp_commit();
        ldg_cvt_Q(query, sm, 0, n0, 0, tid);
        cp_wait0();
        __syncthreads();

        for (int kc = 0; kc < NC_A; kc++) {
            const u32 cur = (u32)(kc & 1) * STG_SZ;
            const u32 nxt = STG_SZ - cur;
            if (kc + 1 < NC_A) {
                stage_S(sb, nxt, b, (kc + 1)*64, tid); cp_commit();
                ldg_cvt_Q(query, sm, nxt, n0, (kc + 1)*64, tid);
            }
            #pragma unroll
            for (int kk2 = 0; kk2 < 4; kk2++) {
                const u32 kb = kk2 * 32;       // 16 k * 2B
                u32 ah[4];
                ldsm_x4(ah, sb + cur + QH_O + arow*144 + kb + aoff);
                #pragma unroll
                for (int p = 0; p < 4; p++) {  // pair of 16-r strips
                    u32 bha[4], bhb[4];
                    u32 bra = ((2*p  )*16 + browoff)*144 + kb + boff;
                    u32 brb = ((2*p+1)*16 + browoff)*144 + kb + boff;
                    ldsm_x4(bha, sb + cur + SH_O + bra);
                    ldsm_x4(bhb, sb + cur + SH_O + brb);
                    float* a0 = acc[4*p+0]; float* a1 = acc[4*p+1];
                    float* a2 = acc[4*p+2]; float* a3 = acc[4*p+3];
                    mma_f16(a0, ah, bha[0], bha[1]);
                    mma_f16(a2, ah, bhb[0], bhb[1]);
                    mma_f16(a1, ah, bha[2], bha[3]);
                    mma_f16(a3, ah, bhb[2], bhb[3]);
                }
            }
            cp_wait0();
            __syncthreads();
        }

        // ====== softmax -> P A-fragments IN PLACE (fp16, into acc[2h]) ======
        #pragma unroll
        for (int h = 0; h < 8; h++) {
            float c0 = Cs[h*16 + 2*qc],     c1 = Cs[h*16 + 2*qc + 1];
            float c2 = Cs[h*16 + 8 + 2*qc], c3 = Cs[h*16 + 8 + 2*qc + 1];
            u32 th[4];
            #pragma unroll
            for (int t = 0; t < 2; t++) {
                float v0 = acc[2*h][2*t]     + c0;
                float v1 = acc[2*h][2*t+1]   + c1;
                float v2 = acc[2*h+1][2*t]   + c2;
                float v3 = acc[2*h+1][2*t+1] + c3;
                float mx = fmaxf(fmaxf(v0, v1), fmaxf(v2, v3));
                mx = fmaxf(mx, __shfl_xor_sync(0xFFFFFFFFu, mx, 1));
                mx = fmaxf(mx, __shfl_xor_sync(0xFFFFFFFFu, mx, 2));
                float e0 = __expf(v0 - mx), e1 = __expf(v1 - mx);
                float e2 = __expf(v2 - mx), e3 = __expf(v3 - mx);
                float s = e0 + e1 + e2 + e3;
                s += __shfl_xor_sync(0xFFFFFFFFu, s, 1);
                s += __shfl_xor_sync(0xFFFFFFFFu, s, 2);
                float inv = 1.f / s;
                th[t]     = pack2h(e0*inv, e1*inv);
                th[2 + t] = pack2h(e2*inv, e3*inv);
            }
            #pragma unroll
            for (int i = 0; i < 4; i++)
                acc[2*h][i] = __uint_as_float(th[i]);
        }

        // ================= Phase C: out = P @ T_b + bo (pipelined) ==========
        stage_T(sb, 0, b, 0, tid); cp_commit();
        cp_wait0();
        __syncthreads();

        for (int ec = 0; ec < NC_C; ec++) {
            const u32 cur = (u32)(ec & 1) * STG_SZ;
            const u32 nxt = STG_SZ - cur;
            if (ec + 1 < NC_C) { stage_T(sb, nxt, b, (ec + 1)*128, tid); cp_commit(); }

            const int e0 = ec * 128;
            #pragma unroll
            for (int np = 0; np < 4; np++) {       // pair of 16-e strips
                float oc[4][4];
                #pragma unroll
                for (int i = 0; i < 4; i++)
                    #pragma unroll
                    for (int j = 0; j < 4; j++) oc[i][j] = 0.f;

                #pragma unroll
                for (int j = 0; j < 8; j++) {
                    u32 ah4[4];
                    #pragma unroll
                    for (int i = 0; i < 4; i++)
                        ah4[i] = __float_as_uint(acc[2*j][i]);
                    u32 bha[4], bhb[4];
                    u32 bra = ((2*np  )*16 + browoff)*272 + j*32 + boff;
                    u32 brb = ((2*np+1)*16 + browoff)*272 + j*32 + boff;
                    ldsm_x4(bha, sb + cur + TH_O + bra);
                    ldsm_x4(bhb, sb + cur + TH_O + brb);
                    mma_f16(oc[0], ah4, bha[0], bha[1]);
                    mma_f16(oc[2], ah4, bhb[0], bhb[1]);
                    mma_f16(oc[1], ah4, bha[2], bha[3]);
                    mma_f16(oc[3], ah4, bhb[2], bhb[3]);
                }
                #pragma unroll
                for (int t = 0; t < 2; t++) {
                    int mrow = m0 + qr + t*8;
                    if (bt[mrow] == b) {
                        #pragma unroll
                        for (int s = 0; s < 4; s++) {
                            int e = e0 + np*32 + (s >> 1)*16 + (s & 1)*8 + 2*qc;
                            float2 w;
                            w.x = oc[s][2*t]   + bos[e];
                            w.y = oc[s][2*t+1] + bos[e+1];
                            *(float2*)(out + (long long)(n0 + mrow)*EMBED + e) = w;
                        }
                    }
                }
            }
            cp_wait0();
            __syncthreads();
        }
    }
}

// ---------------------------------------------------------------------------
extern "C" void kernel_launch(void* const* d_in, const int* in_sizes, int n_in,
                              void* d_out, int out_size) {
    const float* query = (const float*)d_in[0];
    const float* key   = (const float*)d_in[1];
    const float* value = (const float*)d_in[2];
    const int*   bidx  = (const int*)  d_in[3];
    const int off = (n_in >= 13) ? 5 : 4;   // skip scalar batch_size if present
    const float* Wq = (const float*)d_in[off + 0];
    const float* bq = (const float*)d_in[off + 1];
    const float* Wk = (const float*)d_in[off + 2];
    const float* bk = (const float*)d_in[off + 3];
    const float* Wv = (const float*)d_in[off + 4];
    const float* bv = (const float*)d_in[off + 5];
    const float* Wo = (const float*)d_in[off + 6];
    const float* bo = (const float*)d_in[off + 7];
    float* out = (float*)d_out;

    cudaFuncSetAttribute(attn_mma_kernel,
                         cudaFuncAttributeMaxDynamicSharedMemorySize, SMEM_ATTN);

    prep_kernel<<<128, 256>>>(key, value, Wk, bk, Wv, bv, Wq, bq, Wo);
    attn_mma_kernel<<<N_TOKS / TM, 256, SMEM_ATTN>>>(query, bidx, bo, out);
}

// round 16
// speedup vs baseline: 1.3230x; 1.3230x over previous
#include <cuda_runtime.h>
#include <cuda_fp16.h>

#define N_TOKS 32768
#define EMBED  512
#define NCLS   16
#define NBATCH 8
#define NHEAD  8
#define DHEAD  64
#define RDIM   128
#define SCALE  0.125f
#define TM     128

typedef unsigned int u32;

// fp16 tables (error sources: S/T/Q/P quantization ~2^-11 each)
__device__ __half g_Sh[NBATCH*RDIM*EMBED];   // [b][r][k]
__device__ __half g_Th[NBATCH*EMBED*RDIM];   // [b][e][r]
__device__ float g_C[NBATCH*RDIM];

// ---------------- PTX helpers (family-portable) ----------------
__device__ __forceinline__ u32 smem_u32(const void* p) {
    u32 a;
    asm("{ .reg .u64 t; cvta.to.shared.u64 t, %1; cvt.u32.u64 %0, t; }" : "=r"(a) : "l"(p));
    return a;
}
__device__ __forceinline__ void ldsm_x4(u32* r, u32 addr) {
    asm volatile("ldmatrix.sync.aligned.m8n8.x4.shared.b16 {%0,%1,%2,%3}, [%4];"
                 : "=r"(r[0]), "=r"(r[1]), "=r"(r[2]), "=r"(r[3]) : "r"(addr));
}
__device__ __forceinline__ void mma_f16(float* c, const u32* a, u32 b0, u32 b1) {
    asm volatile("mma.sync.aligned.m16n8k16.row.col.f32.f16.f16.f32 "
                 "{%0,%1,%2,%3}, {%4,%5,%6,%7}, {%8,%9}, {%0,%1,%2,%3};"
                 : "+f"(c[0]), "+f"(c[1]), "+f"(c[2]), "+f"(c[3])
                 : "r"(a[0]), "r"(a[1]), "r"(a[2]), "r"(a[3]), "r"(b0), "r"(b1));
}
__device__ __forceinline__ void cp16(u32 dst, const void* src) {
    asm volatile("cp.async.cg.shared.global [%0], [%1], 16;" :: "r"(dst), "l"(src));
}
__device__ __forceinline__ void cp_commit() {
    asm volatile("cp.async.commit_group;" ::: "memory");
}
__device__ __forceinline__ void cp_wait0() {
    asm volatile("cp.async.wait_group 0;" ::: "memory");
}
__device__ __forceinline__ u32 pack2h(float x, float y) {
    __half hx = __float2half_rn(x), hy = __float2half_rn(y);
    return (u32)__half_as_ushort(hx) | ((u32)__half_as_ushort(hy) << 16);
}

// ---------------------------------------------------------------------------
// Fused prep: per (mat,h,b): phase1 KP/VP slice in smem, then fold
// Wq->S(+C) or Wo->T directly. grid=128: mat=x&1, h=(x>>1)&7, b=(x>>4)&7
// ---------------------------------------------------------------------------
__global__ __launch_bounds__(256)
void prep_kernel(const float* __restrict__ key, const float* __restrict__ value,
                 const float* __restrict__ Wk, const float* __restrict__ bk,
                 const float* __restrict__ Wv, const float* __restrict__ bv,
                 const float* __restrict__ Wq, const float* __restrict__ bq,
                 const float* __restrict__ Wo) {
    __shared__ float Ks[16][65];
    __shared__ float KPs[16][65];
    __shared__ float Ws[64][129];

    const int x = blockIdx.x;
    const int mat = x & 1;
    const int h   = (x >> 1) & 7;
    const int b   = (x >> 4) & 7;
    const int tid = threadIdx.x;

    const float* src = mat ? value : key;
    const float* W1  = mat ? Wv : Wk;
    const float* b1  = mat ? bv : bk;

    // ---- phase 1: KP[l][d] = sum_e src[l,b,e]*W1[h*64+d,e] + b1 (in smem) ----
    const int kl  = tid >> 4, ke4 = tid & 15;
    const int d   = tid & 63;
    const int lg4 = tid >> 6;
    {
        float acc[4] = {0.f, 0.f, 0.f, 0.f};
        float4 kbuf, wbuf[4];
        kbuf = *(const float4*)(src + (kl*NBATCH + b)*EMBED + ke4*4);
        #pragma unroll
        for (int i = 0; i < 4; i++) {
            int idx = tid + i*256; int dd = idx >> 4, e4 = idx & 15;
            wbuf[i] = *(const float4*)(W1 + (h*DHEAD + dd)*EMBED + e4*4);
        }
        for (int e0 = 0; e0 < EMBED; e0 += 64) {
            Ks[kl][ke4*4+0] = kbuf.x; Ks[kl][ke4*4+1] = kbuf.y;
            Ks[kl][ke4*4+2] = kbuf.z; Ks[kl][ke4*4+3] = kbuf.w;
            #pragma unroll
            for (int i = 0; i < 4; i++) {
                int idx = tid + i*256; int dd = idx >> 4, e4 = idx & 15;
                Ws[dd][e4*4+0] = wbuf[i].x; Ws[dd][e4*4+1] = wbuf[i].y;
                Ws[dd][e4*4+2] = wbuf[i].z; Ws[dd][e4*4+3] = wbuf[i].w;
            }
            __syncthreads();
            if (e0 + 64 < EMBED) {
                kbuf = *(const float4*)(src + (kl*NBATCH + b)*EMBED + e0 + 64 + ke4*4);
                #pragma unroll
                for (int i = 0; i < 4; i++) {
                    int idx = tid + i*256; int dd = idx >> 4, e4 = idx & 15;
                    wbuf[i] = *(const float4*)(W1 + (h*DHEAD + dd)*EMBED + e0 + 64 + e4*4);
                }
            }
            #pragma unroll 8
            for (int e = 0; e < 64; e++) {
                float wv = Ws[d][e];
                #pragma unroll
                for (int i = 0; i < 4; i++) acc[i] += Ks[lg4*4 + i][e] * wv;
            }
            __syncthreads();
        }
        float bias = b1[h*DHEAD + d];
        #pragma unroll
        for (int i = 0; i < 4; i++) KPs[lg4*4 + i][d] = acc[i] + bias;
    }
    __syncthreads();

    // ---- fold: 4 f-chunks of 128 ----
    const int fcc = tid & 127, lg = tid >> 7;
    if (mat == 0 && tid < 16) {
        float c = 0.f;
        #pragma unroll 8
        for (int dd = 0; dd < DHEAD; dd++) c += KPs[tid][dd] * bq[h*DHEAD + dd];
        g_C[b*RDIM + h*NCLS + tid] = c * SCALE;
    }

    for (int fc = 0; fc < 4; fc++) {
        const int f0 = fc * 128;
        if (mat == 0) {
            #pragma unroll
            for (int i = 0; i < 8; i++) {      // Wq slice 64d x 128f
                int idx = tid + i*256; int dd = idx >> 5, f4 = idx & 31;
                float4 v = *(const float4*)(Wq + (h*DHEAD + dd)*EMBED + f0 + f4*4);
                Ws[dd][f4*4+0] = v.x; Ws[dd][f4*4+1] = v.y;
                Ws[dd][f4*4+2] = v.z; Ws[dd][f4*4+3] = v.w;
            }
        } else {
            #pragma unroll
            for (int i = 0; i < 8; i++) {      // Wo slice: 128e rows x 64d
                int idx = tid + i*256; int e = idx >> 4, d4 = idx & 15;
                float4 v = *(const float4*)(Wo + (f0 + e)*EMBED + h*DHEAD + d4*4);
                Ws[d4*4+0][e] = v.x; Ws[d4*4+1][e] = v.y;
                Ws[d4*4+2][e] = v.z; Ws[d4*4+3][e] = v.w;
            }
        }
        __syncthreads();

        float a2[8] = {0,0,0,0,0,0,0,0};
        #pragma unroll 8
        for (int dd = 0; dd < DHEAD; dd++) {
            float wv = Ws[dd][fcc];
            #pragma unroll
            for (int i = 0; i < 8; i++) a2[i] += KPs[lg*8 + i][dd] * wv;
        }

        if (mat == 0) {
            #pragma unroll
            for (int i = 0; i < 8; i++) {
                int r = h*NCLS + lg*8 + i;
                g_Sh[(b*RDIM + r)*EMBED + f0 + fcc] = __float2half_rn(a2[i] * SCALE);
            }
        } else {
            u32 hw[4];
            #pragma unroll
            for (int i = 0; i < 4; i++)
                hw[i] = pack2h(a2[2*i], a2[2*i+1]);
            long long ofs = ((long long)(b*EMBED + f0 + fcc))*RDIM + h*NCLS + lg*8;
            *(uint4*)&g_Th[ofs] = make_uint4(hw[0], hw[1], hw[2], hw[3]);
        }
        __syncthreads();
    }
}

// ---------------------------------------------------------------------------
// Main attention kernel: 2 blocks per 128-token tile (batch-split for load
// balance at batch boundaries). Single fp16 pass, double-buffered cp.async.
// ---------------------------------------------------------------------------
#define STG_SZ  36864
#define QH_O    0        // 128 rows x 144B (128B data + 16 pad)
#define SH_O    18432    // 128 rows x 144B
#define TH_O    0        // Phase C alias: 64 rows x 272B (256B + 16 pad)
#define SM_BOS  73728
#define SM_CS   75776
#define SM_BT   76288
#define SMEM_ATTN 76800
#define NC_A 8
#define NC_C 8

__device__ __forceinline__ void stage_S(u32 sb, u32 stg, int b, int k0, int tid) {
    #pragma unroll
    for (int i = 0; i < 4; i++) {             // 128 rows x 8 parts of 16B
        int o = tid + i*256;
        int rr = o >> 3, part = o & 7;
        const __half* src = g_Sh + (long long)(b*RDIM + rr)*EMBED + k0 + part*8;
        cp16(sb + stg + SH_O + rr*144 + part*16, src);
    }
}
__device__ __forceinline__ void stage_T(u32 sb, u32 stg, int b, int e0, int tid) {
    #pragma unroll
    for (int i = 0; i < 4; i++) {
        int o = tid + i*256;
        int rr = o >> 4, part = o & 15;
        const __half* src = g_Th + (long long)(b*EMBED + e0 + rr)*RDIM + part*8;
        cp16(sb + stg + TH_O + rr*272 + part*16, src);
    }
}
// load 64-k Q chunk (f32) and convert to fp16 tile (two half-passes, low liveness)
__device__ __forceinline__ void ldg_cvt_Q(const float* __restrict__ query,
                                          char* sm, u32 stg, int n0, int k0, int tid) {
    #pragma unroll
    for (int half = 0; half < 2; half++) {
        float4 qv[4];
        #pragma unroll
        for (int i = 0; i < 4; i++) {
            int id = tid + (half*4 + i)*256;   // 2048 float4 = 128 rows x 16 c4
            int row = id >> 4, c4 = id & 15;
            qv[i] = *(const float4*)(query + (long long)(n0 + row)*EMBED + k0 + c4*4);
        }
        #pragma unroll
        for (int i = 0; i < 4; i++) {
            int id = tid + (half*4 + i)*256;
            int row = id >> 4, c4 = id & 15;
            uint2 hv;
            hv.x = pack2h(qv[i].x, qv[i].y);
            hv.y = pack2h(qv[i].z, qv[i].w);
            *(uint2*)(sm + stg + QH_O + row*144 + c4*8) = hv;
        }
    }
}

__global__ __launch_bounds__(256, 2)
void attn_mma_kernel(const float* __restrict__ query,
                     const int*   __restrict__ bidx,
                     const float* __restrict__ bo,
                     float*       __restrict__ out) {
    extern __shared__ char sm[];
    const u32 sb = smem_u32(sm);

    const int tid  = threadIdx.x;
    const int lane = tid & 31, wid = tid >> 5;
    const int tile = blockIdx.x >> 1;
    const int copy = blockIdx.x & 1;
    const int n0   = tile * TM;
    const int m0   = wid * 16;
    const int qr   = lane >> 2;
    const int qc   = lane & 3;

    int* bt = (int*)(sm + SM_BT);
    if (tid < TM) bt[tid] = bidx[n0 + tid];
    __syncthreads();
    const int b_lo = bt[0], b_hi = bt[TM - 1];

    // batch-split: copy 0 -> [b_lo..mid], copy 1 -> [mid+1..b_hi]
    const int mid   = (b_lo + b_hi) >> 1;
    const int mb_lo = copy ? mid + 1 : b_lo;
    const int mb_hi = copy ? b_hi    : mid;
    if (mb_lo > mb_hi) return;

    float* bos = (float*)(sm + SM_BOS);
    float* Cs  = (float*)(sm + SM_CS);
    bos[tid]       = bo[tid];
    bos[tid + 256] = bo[tid + 256];
    __syncthreads();

    const u32 arow    = m0 + (lane & 15);
    const u32 aoff    = (u32)(lane >> 4) << 4;          // 0/16B: k+0 / k+8
    const u32 browoff = ((lane >> 4) << 3) + (lane & 7);
    const u32 boff    = (u32)((lane >> 3) & 1) << 4;    // 0/16B

    for (int b = mb_lo; b <= mb_hi; b++) {
        if (tid < 128) Cs[tid] = g_C[b*RDIM + tid];

        // ================= Phase A: scores = Q @ S_b^T (pipelined) ==========
        float acc[16][4];
        #pragma unroll
        for (int i = 0; i < 16; i++)
            #pragma unroll
            for (int j = 0; j < 4; j++) acc[i][j] = 0.f;

        stage_S(sb, 0, b, 0, tid); cp_commit();
        ldg_cvt_Q(query, sm, 0, n0, 0, tid);
        cp_wait0();
        __syncthreads();

        for (int kc = 0; kc < NC_A; kc++) {
            const u32 cur = (u32)(kc & 1) * STG_SZ;
            const u32 nxt = STG_SZ - cur;
            if (kc + 1 < NC_A) {
                stage_S(sb, nxt, b, (kc + 1)*64, tid); cp_commit();
                ldg_cvt_Q(query, sm, nxt, n0, (kc + 1)*64, tid);
            }
            #pragma unroll
            for (int kk2 = 0; kk2 < 4; kk2++) {
                const u32 kb = kk2 * 32;       // 16 k * 2B
                u32 ah[4];
                ldsm_x4(ah, sb + cur + QH_O + arow*144 + kb + aoff);
                #pragma unroll
                for (int p = 0; p < 4; p++) {  // pair of 16-r strips
                    u32 bha[4], bhb[4];
                    u32 bra = ((2*p  )*16 + browoff)*144 + kb + boff;
                    u32 brb = ((2*p+1)*16 + browoff)*144 + kb + boff;
                    ldsm_x4(bha, sb + cur + SH_O + bra);
                    ldsm_x4(bhb, sb + cur + SH_O + brb);
                    float* a0 = acc[4*p+0]; float* a1 = acc[4*p+1];
                    float* a2 = acc[4*p+2]; float* a3 = acc[4*p+3];
                    mma_f16(a0, ah, bha[0], bha[1]);
                    mma_f16(a2, ah, bhb[0], bhb[1]);
                    mma_f16(a1, ah, bha[2], bha[3]);
                    mma_f16(a3, ah, bhb[2], bhb[3]);
                }
            }
            cp_wait0();
            __syncthreads();
        }

        // ====== softmax -> P A-fragments IN PLACE (fp16, into acc[2h]) ======
        #pragma unroll
        for (int h = 0; h < 8; h++) {
            float c0 = Cs[h*16 + 2*qc],     c1 = Cs[h*16 + 2*qc + 1];
            float c2 = Cs[h*16 + 8 + 2*qc], c3 = Cs[h*16 + 8 + 2*qc + 1];
            u32 th[4];
            #pragma unroll
            for (int t = 0; t < 2; t++) {
                float v0 = acc[2*h][2*t]     + c0;
                float v1 = acc[2*h][2*t+1]   + c1;
                float v2 = acc[2*h+1][2*t]   + c2;
                float v3 = acc[2*h+1][2*t+1] + c3;
                float mx = fmaxf(fmaxf(v0, v1), fmaxf(v2, v3));
                mx = fmaxf(mx, __shfl_xor_sync(0xFFFFFFFFu, mx, 1));
                mx = fmaxf(mx, __shfl_xor_sync(0xFFFFFFFFu, mx, 2));
                float e0 = __expf(v0 - mx), e1 = __expf(v1 - mx);
                float e2 = __expf(v2 - mx), e3 = __expf(v3 - mx);
                float s = e0 + e1 + e2 + e3;
                s += __shfl_xor_sync(0xFFFFFFFFu, s, 1);
                s += __shfl_xor_sync(0xFFFFFFFFu, s, 2);
                float inv = 1.f / s;
                th[t]     = pack2h(e0*inv, e1*inv);
                th[2 + t] = pack2h(e2*inv, e3*inv);
            }
            #pragma unroll
            for (int i = 0; i < 4; i++)
                acc[2*h][i] = __uint_as_float(th[i]);
        }

        // ================= Phase C: out = P @ T_b + bo (pipelined) ==========
        stage_T(sb, 0, b, 0, tid); cp_commit();
        cp_wait0();
        __syncthreads();

        for (int ec = 0; ec < NC_C; ec++) {
            const u32 cur = (u32)(ec & 1) * STG_SZ;
            const u32 nxt = STG_SZ - cur;
            if (ec + 1 < NC_C) { stage_T(sb, nxt, b, (ec + 1)*64, tid); cp_commit(); }

            const int e0 = ec * 64;
            #pragma unroll
            for (int np = 0; np < 2; np++) {       // pair of 16-e strips
                float oc[4][4];
                #pragma unroll
                for (int i = 0; i < 4; i++)
                    #pragma unroll
                    for (int j = 0; j < 4; j++) oc[i][j] = 0.f;

                #pragma unroll
                for (int j = 0; j < 8; j++) {
                    u32 ah4[4];
                    #pragma unroll
                    for (int i = 0; i < 4; i++)
                        ah4[i] = __float_as_uint(acc[2*j][i]);
                    u32 bha[4], bhb[4];
                    u32 bra = ((2*np  )*16 + browoff)*272 + j*32 + boff;
                    u32 brb = ((2*np+1)*16 + browoff)*272 + j*32 + boff;
                    ldsm_x4(bha, sb + cur + TH_O + bra);
                    ldsm_x4(bhb, sb + cur + TH_O + brb);
                    mma_f16(oc[0], ah4, bha[0], bha[1]);
                    mma_f16(oc[2], ah4, bhb[0], bhb[1]);
                    mma_f16(oc[1], ah4, bha[2], bha[3]);
                    mma_f16(oc[3], ah4, bhb[2], bhb[3]);
                }
                #pragma unroll
                for (int t = 0; t < 2; t++) {
                    int mrow = m0 + qr + t*8;
                    if (bt[mrow] == b) {
                        #pragma unroll
                        for (int s = 0; s < 4; s++) {
                            int e = e0 + np*32 + (s >> 1)*16 + (s & 1)*8 + 2*qc;
                            float2 w;
                            w.x = oc[s][2*t]   + bos[e];
                            w.y = oc[s][2*t+1] + bos[e+1];
                            *(float2*)(out + (long long)(n0 + mrow)*EMBED + e) = w;
                        }
                    }
                }
            }
            cp_wait0();
            __syncthreads();
        }
    }
}

// ---------------------------------------------------------------------------
extern "C" void kernel_launch(void* const* d_in, const int* in_sizes, int n_in,
                              void* d_out, int out_size) {
    const float* query = (const float*)d_in[0];
    const float* key   = (const float*)d_in[1];
    const float* value = (const float*)d_in[2];
    const int*   bidx  = (const int*)  d_in[3];
    const int off = (n_in >= 13) ? 5 : 4;   // skip scalar batch_size if present
    const float* Wq = (const float*)d_in[off + 0];
    const float* bq = (const float*)d_in[off + 1];
    const float* Wk = (const float*)d_in[off + 2];
    const float* bk = (const float*)d_in[off + 3];
    const float* Wv = (const float*)d_in[off + 4];
    const float* bv = (const float*)d_in[off + 5];
    const float* Wo = (const float*)d_in[off + 6];
    const float* bo = (const float*)d_in[off + 7];
    float* out = (float*)d_out;

    cudaFuncSetAttribute(attn_mma_kernel,
                         cudaFuncAttributeMaxDynamicSharedMemorySize, SMEM_ATTN);

    prep_kernel<<<128, 256>>>(key, value, Wk, bk, Wv, bv, Wq, bq, Wo);
    attn_mma_kernel<<<2 * (N_TOKS / TM), 256, SMEM_ATTN>>>(query, bidx, bo, out);
}

// round 17
// speedup vs baseline: 1.3524x; 1.0222x over previous
#include <cuda_runtime.h>
#include <cuda_fp16.h>

#define N_TOKS 32768
#define EMBED  512
#define NCLS   16
#define NBATCH 8
#define NHEAD  8
#define DHEAD  64
#define RDIM   128
#define SCALE  0.125f
#define TM     128

typedef unsigned int u32;

// fp16 tables (error sources: S/T/Q/P quantization ~2^-11 each)
__device__ __half g_Sh[NBATCH*RDIM*EMBED];   // [b][r][k]
__device__ __half g_Th[NBATCH*EMBED*RDIM];   // [b][e][r]
__device__ float g_C[NBATCH*RDIM];
// phase-1 partials: [mat][b][h][eq][l][d]
__device__ float g_part[2*NBATCH*NHEAD*4*16*DHEAD];

// ---------------- PTX helpers (family-portable) ----------------
__device__ __forceinline__ u32 smem_u32(const void* p) {
    u32 a;
    asm("{ .reg .u64 t; cvta.to.shared.u64 t, %1; cvt.u32.u64 %0, t; }" : "=r"(a) : "l"(p));
    return a;
}
__device__ __forceinline__ void ldsm_x4(u32* r, u32 addr) {
    asm volatile("ldmatrix.sync.aligned.m8n8.x4.shared.b16 {%0,%1,%2,%3}, [%4];"
                 : "=r"(r[0]), "=r"(r[1]), "=r"(r[2]), "=r"(r[3]) : "r"(addr));
}
__device__ __forceinline__ void mma_f16(float* c, const u32* a, u32 b0, u32 b1) {
    asm volatile("mma.sync.aligned.m16n8k16.row.col.f32.f16.f16.f32 "
                 "{%0,%1,%2,%3}, {%4,%5,%6,%7}, {%8,%9}, {%0,%1,%2,%3};"
                 : "+f"(c[0]), "+f"(c[1]), "+f"(c[2]), "+f"(c[3])
                 : "r"(a[0]), "r"(a[1]), "r"(a[2]), "r"(a[3]), "r"(b0), "r"(b1));
}
__device__ __forceinline__ void cp16(u32 dst, const void* src) {
    asm volatile("cp.async.cg.shared.global [%0], [%1], 16;" :: "r"(dst), "l"(src));
}
__device__ __forceinline__ void cp_commit() {
    asm volatile("cp.async.commit_group;" ::: "memory");
}
__device__ __forceinline__ void cp_wait0() {
    asm volatile("cp.async.wait_group 0;" ::: "memory");
}
__device__ __forceinline__ u32 pack2h(float x, float y) {
    __half hx = __float2half_rn(x), hy = __float2half_rn(y);
    return (u32)__half_as_ushort(hx) | ((u32)__half_as_ushort(hy) << 16);
}

// ---------------------------------------------------------------------------
// P1: phase-1 partials. grid=512: eq=x&3, b=(x>>2)&7, h=(x>>5)&7, mat=x>>8.
// part[l][d] = sum_{e in eq-chunk} src[l,b,e] * W1[h*64+d, e]
// ---------------------------------------------------------------------------
__global__ __launch_bounds__(256)
void partial_kernel(const float* __restrict__ key, const float* __restrict__ value,
                    const float* __restrict__ Wk, const float* __restrict__ Wv) {
    __shared__ float Ks[16][129];
    __shared__ float Ws[64][129];

    const int x   = blockIdx.x;
    const int eq  = x & 3;
    const int b   = (x >> 2) & 7;
    const int h   = (x >> 5) & 7;
    const int mat = x >> 8;
    const int tid = threadIdx.x;
    const int e0  = eq * 128;

    const float* src = mat ? value : key;
    const float* W1  = mat ? Wv : Wk;

    #pragma unroll
    for (int i = 0; i < 2; i++) {          // 16 rows x 128 e
        int id = tid + i*256; int row = id >> 5, c4 = id & 31;
        float4 v = *(const float4*)(src + (row*NBATCH + b)*EMBED + e0 + c4*4);
        Ks[row][c4*4+0] = v.x; Ks[row][c4*4+1] = v.y;
        Ks[row][c4*4+2] = v.z; Ks[row][c4*4+3] = v.w;
    }
    #pragma unroll
    for (int i = 0; i < 8; i++) {          // 64 d x 128 e
        int id = tid + i*256; int dd = id >> 5, c4 = id & 31;
        float4 v = *(const float4*)(W1 + (h*DHEAD + dd)*EMBED + e0 + c4*4);
        Ws[dd][c4*4+0] = v.x; Ws[dd][c4*4+1] = v.y;
        Ws[dd][c4*4+2] = v.z; Ws[dd][c4*4+3] = v.w;
    }
    __syncthreads();

    const int d = tid & 63, lg4 = tid >> 6;
    float acc[4] = {0.f, 0.f, 0.f, 0.f};
    #pragma unroll 8
    for (int e = 0; e < 128; e++) {
        float wv = Ws[d][e];
        #pragma unroll
        for (int i = 0; i < 4; i++) acc[i] += Ks[lg4*4 + i][e] * wv;
    }
    float* dst = g_part + (long long)(((mat*NBATCH + b)*NHEAD + h)*4 + eq) * 1024;
    #pragma unroll
    for (int i = 0; i < 4; i++)
        dst[(lg4*4 + i)*DHEAD + d] = acc[i];
}

// ---------------------------------------------------------------------------
// P2: fold Wq->S(+C), Wo->T from partial sums. grid=512:
// fc=x&3, b=(x>>2)&7, h=(x>>5)&7, isT=x>>8
// ---------------------------------------------------------------------------
__global__ __launch_bounds__(256)
void fold_kernel(const float* __restrict__ Wq, const float* __restrict__ bq,
                 const float* __restrict__ Wo,
                 const float* __restrict__ bk, const float* __restrict__ bv) {
    __shared__ float KPs[16][65];
    __shared__ float Ws[64][129];

    const int x   = blockIdx.x;
    const int fc  = x & 3;
    const int b   = (x >> 2) & 7;
    const int h   = (x >> 5) & 7;
    const int isT = x >> 8;
    const int tid = threadIdx.x;
    const int f0  = fc * 128;

    const float* b1 = isT ? bv : bk;
    {   // sum 4 partials + bias -> KPs
        const float* part = g_part + (long long)(((isT*NBATCH + b)*NHEAD + h)*4) * 1024;
        #pragma unroll
        for (int i = 0; i < 4; i++) {
            int id = tid + i*256;          // 1024 elements
            int l = id >> 6, d = id & 63;
            float s = part[id] + part[id + 1024] + part[id + 2048] + part[id + 3072]
                    + b1[h*DHEAD + d];
            KPs[l][d] = s;
        }
    }
    if (!isT) {
        #pragma unroll
        for (int i = 0; i < 8; i++) {      // Wq slice 64d x 128f
            int idx = tid + i*256; int dd = idx >> 5, f4 = idx & 31;
            float4 v = *(const float4*)(Wq + (h*DHEAD + dd)*EMBED + f0 + f4*4);
            Ws[dd][f4*4+0] = v.x; Ws[dd][f4*4+1] = v.y;
            Ws[dd][f4*4+2] = v.z; Ws[dd][f4*4+3] = v.w;
        }
    } else {
        #pragma unroll
        for (int i = 0; i < 8; i++) {      // Wo slice: 128e rows x 64d
            int idx = tid + i*256; int e = idx >> 4, d4 = idx & 15;
            float4 v = *(const float4*)(Wo + (f0 + e)*EMBED + h*DHEAD + d4*4);
            Ws[d4*4+0][e] = v.x; Ws[d4*4+1][e] = v.y;
            Ws[d4*4+2][e] = v.z; Ws[d4*4+3][e] = v.w;
        }
    }
    __syncthreads();

    const int fcc = tid & 127, lg = tid >> 7;
    if (!isT && fc == 0 && tid < 16) {
        float c = 0.f;
        #pragma unroll 8
        for (int dd = 0; dd < DHEAD; dd++) c += KPs[tid][dd] * bq[h*DHEAD + dd];
        g_C[b*RDIM + h*NCLS + tid] = c * SCALE;
    }

    float a2[8] = {0,0,0,0,0,0,0,0};
    #pragma unroll 8
    for (int dd = 0; dd < DHEAD; dd++) {
        float wv = Ws[dd][fcc];
        #pragma unroll
        for (int i = 0; i < 8; i++) a2[i] += KPs[lg*8 + i][dd] * wv;
    }

    if (!isT) {
        #pragma unroll
        for (int i = 0; i < 8; i++) {
            int r = h*NCLS + lg*8 + i;
            g_Sh[(b*RDIM + r)*EMBED + f0 + fcc] = __float2half_rn(a2[i] * SCALE);
        }
    } else {
        u32 hw[4];
        #pragma unroll
        for (int i = 0; i < 4; i++)
            hw[i] = pack2h(a2[2*i], a2[2*i+1]);
        long long ofs = ((long long)(b*EMBED + f0 + fcc))*RDIM + h*NCLS + lg*8;
        *(uint4*)&g_Th[ofs] = make_uint4(hw[0], hw[1], hw[2], hw[3]);
    }
}

// ---------------------------------------------------------------------------
// Main attention kernel: 2 blocks per 128-token tile (batch-split for load
// balance at batch boundaries). Single fp16 pass, double-buffered cp.async.
// ---------------------------------------------------------------------------
#define STG_SZ  36864
#define QH_O    0        // 128 rows x 144B (128B data + 16 pad)
#define SH_O    18432    // 128 rows x 144B
#define TH_O    0        // Phase C alias: 64 rows x 272B (256B + 16 pad)
#define SM_BOS  73728
#define SM_CS   75776
#define SM_BT   76288
#define SMEM_ATTN 76800
#define NC_A 8
#define NC_C 8

__device__ __forceinline__ void stage_S(u32 sb, u32 stg, int b, int k0, int tid) {
    #pragma unroll
    for (int i = 0; i < 4; i++) {             // 128 rows x 8 parts of 16B
        int o = tid + i*256;
        int rr = o >> 3, part = o & 7;
        const __half* src = g_Sh + (long long)(b*RDIM + rr)*EMBED + k0 + part*8;
        cp16(sb + stg + SH_O + rr*144 + part*16, src);
    }
}
__device__ __forceinline__ void stage_T(u32 sb, u32 stg, int b, int e0, int tid) {
    #pragma unroll
    for (int i = 0; i < 4; i++) {
        int o = tid + i*256;
        int rr = o >> 4, part = o & 15;
        const __half* src = g_Th + (long long)(b*EMBED + e0 + rr)*RDIM + part*8;
        cp16(sb + stg + TH_O + rr*272 + part*16, src);
    }
}
// load 64-k Q chunk (f32) and convert to fp16 tile (two half-passes, low liveness)
__device__ __forceinline__ void ldg_cvt_Q(const float* __restrict__ query,
                                          char* sm, u32 stg, int n0, int k0, int tid) {
    #pragma unroll
    for (int half = 0; half < 2; half++) {
        float4 qv[4];
        #pragma unroll
        for (int i = 0; i < 4; i++) {
            int id = tid + (half*4 + i)*256;   // 2048 float4 = 128 rows x 16 c4
            int row = id >> 4, c4 = id & 15;
            qv[i] = *(const float4*)(query + (long long)(n0 + row)*EMBED + k0 + c4*4);
        }
        #pragma unroll
        for (int i = 0; i < 4; i++) {
            int id = tid + (half*4 + i)*256;
            int row = id >> 4, c4 = id & 15;
            uint2 hv;
            hv.x = pack2h(qv[i].x, qv[i].y);
            hv.y = pack2h(qv[i].z, qv[i].w);
            *(uint2*)(sm + stg + QH_O + row*144 + c4*8) = hv;
        }
    }
}

__global__ __launch_bounds__(256, 2)
void attn_mma_kernel(const float* __restrict__ query,
                     const int*   __restrict__ bidx,
                     const float* __restrict__ bo,
                     float*       __restrict__ out) {
    extern __shared__ char sm[];
    const u32 sb = smem_u32(sm);

    const int tid  = threadIdx.x;
    const int lane = tid & 31, wid = tid >> 5;
    const int tile = blockIdx.x >> 1;
    const int copy = blockIdx.x & 1;
    const int n0   = tile * TM;
    const int m0   = wid * 16;
    const int qr   = lane >> 2;
    const int qc   = lane & 3;

    int* bt = (int*)(sm + SM_BT);
    if (tid < TM) bt[tid] = bidx[n0 + tid];
    __syncthreads();
    const int b_lo = bt[0], b_hi = bt[TM - 1];

    // batch-split: copy 0 -> [b_lo..mid], copy 1 -> [mid+1..b_hi]
    const int mid   = (b_lo + b_hi) >> 1;
    const int mb_lo = copy ? mid + 1 : b_lo;
    const int mb_hi = copy ? b_hi    : mid;
    if (mb_lo > mb_hi) return;

    float* bos = (float*)(sm + SM_BOS);
    float* Cs  = (float*)(sm + SM_CS);
    bos[tid]       = bo[tid];
    bos[tid + 256] = bo[tid + 256];
    __syncthreads();

    const u32 arow    = m0 + (lane & 15);
    const u32 aoff    = (u32)(lane >> 4) << 4;          // 0/16B: k+0 / k+8
    const u32 browoff = ((lane >> 4) << 3) + (lane & 7);
    const u32 boff    = (u32)((lane >> 3) & 1) << 4;    // 0/16B

    for (int b = mb_lo; b <= mb_hi; b++) {
        if (tid < 128) Cs[tid] = g_C[b*RDIM + tid];

        // ================= Phase A: scores = Q @ S_b^T (pipelined) ==========
        float acc[16][4];
        #pragma unroll
        for (int i = 0; i < 16; i++)
            #pragma unroll
            for (int j = 0; j < 4; j++) acc[i][j] = 0.f;

        stage_S(sb, 0, b, 0, tid); cp_commit();
        ldg_cvt_Q(query, sm, 0, n0, 0, tid);
        cp_wait0();
        __syncthreads();

        for (int kc = 0; kc < NC_A; kc++) {
            const u32 cur = (u32)(kc & 1) * STG_SZ;
            const u32 nxt = STG_SZ - cur;
            if (kc + 1 < NC_A) {
                stage_S(sb, nxt, b, (kc + 1)*64, tid); cp_commit();
                ldg_cvt_Q(query, sm, nxt, n0, (kc + 1)*64, tid);
            }
            #pragma unroll
            for (int kk2 = 0; kk2 < 4; kk2++) {
                const u32 kb = kk2 * 32;       // 16 k * 2B
                u32 ah[4];
                ldsm_x4(ah, sb + cur + QH_O + arow*144 + kb + aoff);
                #pragma unroll
                for (int p = 0; p < 4; p++) {  // pair of 16-r strips
                    u32 bha[4], bhb[4];
                    u32 bra = ((2*p  )*16 + browoff)*144 + kb + boff;
                    u32 brb = ((2*p+1)*16 + browoff)*144 + kb + boff;
                    ldsm_x4(bha, sb + cur + SH_O + bra);
                    ldsm_x4(bhb, sb + cur + SH_O + brb);
                    float* a0 = acc[4*p+0]; float* a1 = acc[4*p+1];
                    float* a2 = acc[4*p+2]; float* a3 = acc[4*p+3];
                    mma_f16(a0, ah, bha[0], bha[1]);
                    mma_f16(a2, ah, bhb[0], bhb[1]);
                    mma_f16(a1, ah, bha[2], bha[3]);
                    mma_f16(a3, ah, bhb[2], bhb[3]);
                }
            }
            cp_wait0();
            __syncthreads();
        }

        // ====== softmax -> P A-fragments IN PLACE (fp16, into acc[2h]) ======
        #pragma unroll
        for (int h = 0; h < 8; h++) {
            float c0 = Cs[h*16 + 2*qc],     c1 = Cs[h*16 + 2*qc + 1];
            float c2 = Cs[h*16 + 8 + 2*qc], c3 = Cs[h*16 + 8 + 2*qc + 1];
            u32 th[4];
            #pragma unroll
            for (int t = 0; t < 2; t++) {
                float v0 = acc[2*h][2*t]     + c0;
                float v1 = acc[2*h][2*t+1]   + c1;
                float v2 = acc[2*h+1][2*t]   + c2;
                float v3 = acc[2*h+1][2*t+1] + c3;
                float mx = fmaxf(fmaxf(v0, v1), fmaxf(v2, v3));
                mx = fmaxf(mx, __shfl_xor_sync(0xFFFFFFFFu, mx, 1));
                mx = fmaxf(mx, __shfl_xor_sync(0xFFFFFFFFu, mx, 2));
                float e0 = __expf(v0 - mx), e1 = __expf(v1 - mx);
                float e2 = __expf(v2 - mx), e3 = __expf(v3 - mx);
                float s = e0 + e1 + e2 + e3;
                s += __shfl_xor_sync(0xFFFFFFFFu, s, 1);
                s += __shfl_xor_sync(0xFFFFFFFFu, s, 2);
                float inv = 1.f / s;
                th[t]     = pack2h(e0*inv, e1*inv);
                th[2 + t] = pack2h(e2*inv, e3*inv);
            }
            #pragma unroll
            for (int i = 0; i < 4; i++)
                acc[2*h][i] = __uint_as_float(th[i]);
        }

        // ================= Phase C: out = P @ T_b + bo (pipelined) ==========
        stage_T(sb, 0, b, 0, tid); cp_commit();
        cp_wait0();
        __syncthreads();

        for (int ec = 0; ec < NC_C; ec++) {
            const u32 cur = (u32)(ec & 1) * STG_SZ;
            const u32 nxt = STG_SZ - cur;
            if (ec + 1 < NC_C) { stage_T(sb, nxt, b, (ec + 1)*64, tid); cp_commit(); }

            const int e0 = ec * 64;
            #pragma unroll
            for (int np = 0; np < 2; np++) {       // pair of 16-e strips
                float oc[4][4];
                #pragma unroll
                for (int i = 0; i < 4; i++)
                    #pragma unroll
                    for (int j = 0; j < 4; j++) oc[i][j] = 0.f;

                #pragma unroll
                for (int j = 0; j < 8; j++) {
                    u32 ah4[4];
                    #pragma unroll
                    for (int i = 0; i < 4; i++)
                        ah4[i] = __float_as_uint(acc[2*j][i]);
                    u32 bha[4], bhb[4];
                    u32 bra = ((2*np  )*16 + browoff)*272 + j*32 + boff;
                    u32 brb = ((2*np+1)*16 + browoff)*272 + j*32 + boff;
                    ldsm_x4(bha, sb + cur + TH_O + bra);
                    ldsm_x4(bhb, sb + cur + TH_O + brb);
                    mma_f16(oc[0], ah4, bha[0], bha[1]);
                    mma_f16(oc[2], ah4, bhb[0], bhb[1]);
                    mma_f16(oc[1], ah4, bha[2], bha[3]);
                    mma_f16(oc[3], ah4, bhb[2], bhb[3]);
                }
                #pragma unroll
                for (int t = 0; t < 2; t++) {
                    int mrow = m0 + qr + t*8;
                    if (bt[mrow] == b) {
                        #pragma unroll
                        for (int s = 0; s < 4; s++) {
                            int e = e0 + np*32 + (s >> 1)*16 + (s & 1)*8 + 2*qc;
                            float2 w;
                            w.x = oc[s][2*t]   + bos[e];
                            w.y = oc[s][2*t+1] + bos[e+1];
                            *(float2*)(out + (long long)(n0 + mrow)*EMBED + e) = w;
                        }
                    }
                }
            }
            cp_wait0();
            __syncthreads();
        }
    }
}

// ---------------------------------------------------------------------------
extern "C" void kernel_launch(void* const* d_in, const int* in_sizes, int n_in,
                              void* d_out, int out_size) {
    const float* query = (const float*)d_in[0];
    const float* key   = (const float*)d_in[1];
    const float* value = (const float*)d_in[2];
    const int*   bidx  = (const int*)  d_in[3];
    const int off = (n_in >= 13) ? 5 : 4;   // skip scalar batch_size if present
    const float* Wq = (const float*)d_in[off + 0];
    const float* bq = (const float*)d_in[off + 1];
    const float* Wk = (const float*)d_in[off + 2];
    const float* bk = (const float*)d_in[off + 3];
    const float* Wv = (const float*)d_in[off + 4];
    const float* bv = (const float*)d_in[off + 5];
    const float* Wo = (const float*)d_in[off + 6];
    const float* bo = (const float*)d_in[off + 7];
    float* out = (float*)d_out;

    cudaFuncSetAttribute(attn_mma_kernel,
                         cudaFuncAttributeMaxDynamicSharedMemorySize, SMEM_ATTN);

    partial_kernel<<<512, 256>>>(key, value, Wk, Wv);
    fold_kernel<<<512, 256>>>(Wq, bq, Wo, bk, bv);
    attn_mma_kernel<<<2 * (N_TOKS / TM), 256, SMEM_ATTN>>>(query, bidx, bo, out);
}